// round 2
// baseline (speedup 1.0000x reference)
#include <cuda_runtime.h>

// Problem constants
#define B     1024
#define T     512
#define E     64
#define H     50     // layer-1 hidden
#define G     200    // 4*H gates
#define NB    4      // batches per layer-1 block
#define BPAIR 2      // batch pairs per block (float2-packed over batch)
#define NPAIR (B/2)  // 512 global batch pairs
#define L1_THREADS 128
#define L2_THREADS 128
#define TCH   32     // layer-2 tile chunk (timesteps)

// Scratch: layer-1 hidden states, batch-pair packed.
// [run(0=fwd,1=bwd-run)][batch pair][t (run-step order)][j] ; .x = even batch, .y = odd
__device__ float2 g_h1[2][NPAIR][T][H];   // ~210 MB

__device__ __forceinline__ float sigf(float x) {
    return 1.0f / (1.0f + __expf(-x));
}
__device__ __forceinline__ float tanhfast(float x) {
    // tanh(x) = 2/(1+exp(-2x)) - 1 ; __expf rel err ~1e-6, plenty under 1e-3 tol
    return 2.0f / (1.0f + __expf(-2.0f * x)) - 1.0f;
}

// ---------------------------------------------------------------------------
// Layer-1: bidirectional LSTM, constant input over time.
// grid = (B/NB, 2 dirs), block = 128 threads.
// Threads 0..99: matvec workers, thread t owns gates (2t, 2t+1) for all 4 batches.
// Threads 0..99 also run the epilogue: task (j = tid%50, bp = tid/50).
// ---------------------------------------------------------------------------
__global__ __launch_bounds__(L1_THREADS) void lstm1_kernel(
    const float* __restrict__ x,
    const float* __restrict__ Wih_f, const float* __restrict__ Whh_f,
    const float* __restrict__ bih_f, const float* __restrict__ bhh_f,
    const float* __restrict__ Wih_b, const float* __restrict__ Whh_b,
    const float* __restrict__ bih_b, const float* __restrict__ bhh_b)
{
    // W_hh interleaved tiles: Ws4[jp*100 + t] = (W[2t][2jp], W[2t+1][2jp], W[2t][2jp+1], W[2t+1][2jp+1])
    __shared__ float4 Ws4[(H / 2) * (G / 2)];      // 2500 * 16B = 40000 B
    __shared__ float2 xg_p[BPAIR][G];              // 3200 B  (input+bias contribution, packed)
    __shared__ float2 gates_p[BPAIR][G];           // 3200 B
    __shared__ float2 hp[BPAIR][H + 2];            // pad row to 52 -> 16B-aligned float4 reads
    __shared__ float  xs[NB][E];                   // 1024 B

    const int dir = blockIdx.y;
    const int b0  = blockIdx.x * NB;
    const int tid = threadIdx.x;

    const float* __restrict__ Wih = dir ? Wih_b : Wih_f;
    const float* __restrict__ Whh = dir ? Whh_b : Whh_f;
    const float* __restrict__ bih = dir ? bih_b : bih_f;
    const float* __restrict__ bhh = dir ? bhh_b : bhh_f;

    // Stage x for our 4 batches
    for (int i = tid; i < NB * E; i += L1_THREADS)
        xs[i / E][i % E] = x[(b0 + i / E) * E + (i % E)];

    // Stage W_hh transposed/interleaved
    for (int i = tid; i < (H / 2) * (G / 2); i += L1_THREADS) {
        int jp = i / (G / 2);
        int t  = i % (G / 2);
        float wa = Whh[(2 * t)     * H + 2 * jp];
        float wb = Whh[(2 * t + 1) * H + 2 * jp];
        float wc = Whh[(2 * t)     * H + 2 * jp + 1];
        float wd = Whh[(2 * t + 1) * H + 2 * jp + 1];
        Ws4[i] = make_float4(wa, wb, wc, wd);
    }

    // Zero h state
    for (int i = tid; i < BPAIR * (H + 2); i += L1_THREADS)
        ((float2*)hp)[i] = make_float2(0.f, 0.f);
    __syncthreads();

    // Input projection xg (constant over time): gates (2t, 2t+1) x 4 batches
    if (tid < G / 2) {
        int g0 = 2 * tid, g1 = 2 * tid + 1;
        float bias0 = bih[g0] + bhh[g0];
        float bias1 = bih[g1] + bhh[g1];
        float2 a00 = make_float2(bias0, bias0), a01 = make_float2(bias0, bias0);
        float2 a10 = make_float2(bias1, bias1), a11 = make_float2(bias1, bias1);
        #pragma unroll 8
        for (int e = 0; e < E; e++) {
            float w0 = Wih[g0 * E + e], w1 = Wih[g1 * E + e];
            float x0 = xs[0][e], x1 = xs[1][e], x2 = xs[2][e], x3 = xs[3][e];
            a00.x = fmaf(x0, w0, a00.x); a00.y = fmaf(x1, w0, a00.y);
            a01.x = fmaf(x2, w0, a01.x); a01.y = fmaf(x3, w0, a01.y);
            a10.x = fmaf(x0, w1, a10.x); a10.y = fmaf(x1, w1, a10.y);
            a11.x = fmaf(x2, w1, a11.x); a11.y = fmaf(x3, w1, a11.y);
        }
        xg_p[0][g0] = a00; xg_p[1][g0] = a01;
        xg_p[0][g1] = a10; xg_p[1][g1] = a11;
    }
    __syncthreads();

    // Epilogue task assignment for tid < 100
    const int ej  = tid % H;      // hidden unit
    const int ebp = tid / H;      // batch pair 0/1 (valid for tid<100)
    float2 cst = make_float2(0.f, 0.f);

    for (int step = 0; step < T; step++) {
        // ---- matvec: gates = xg + W_hh * h ----
        if (tid < G / 2) {
            float4 A0 = *(const float4*)&xg_p[0][2 * tid];  // (g0.x,g0.y,g1.x,g1.y) bp0
            float4 A1 = *(const float4*)&xg_p[1][2 * tid];  // bp1
            #pragma unroll
            for (int jp = 0; jp < H / 2; jp++) {
                float4 w  = Ws4[jp * (G / 2) + tid];
                float4 h0 = *(const float4*)&hp[0][2 * jp]; // (hb0[j0],hb1[j0],hb0[j1],hb1[j1])
                float4 h1 = *(const float4*)&hp[1][2 * jp];
                A0.x = fmaf(w.x, h0.x, A0.x); A0.y = fmaf(w.x, h0.y, A0.y);
                A0.z = fmaf(w.y, h0.x, A0.z); A0.w = fmaf(w.y, h0.y, A0.w);
                A0.x = fmaf(w.z, h0.z, A0.x); A0.y = fmaf(w.z, h0.w, A0.y);
                A0.z = fmaf(w.w, h0.z, A0.z); A0.w = fmaf(w.w, h0.w, A0.w);
                A1.x = fmaf(w.x, h1.x, A1.x); A1.y = fmaf(w.x, h1.y, A1.y);
                A1.z = fmaf(w.y, h1.x, A1.z); A1.w = fmaf(w.y, h1.y, A1.w);
                A1.x = fmaf(w.z, h1.z, A1.x); A1.y = fmaf(w.z, h1.w, A1.y);
                A1.z = fmaf(w.w, h1.z, A1.z); A1.w = fmaf(w.w, h1.w, A1.w);
            }
            *(float4*)&gates_p[0][2 * tid] = A0;
            *(float4*)&gates_p[1][2 * tid] = A1;
        }
        __syncthreads();

        // ---- epilogue: activations + state update ----
        if (tid < 100) {
            float2 iv = gates_p[ebp][ej];
            float2 fv = gates_p[ebp][ej + H];
            float2 gv = gates_p[ebp][ej + 2 * H];
            float2 ov = gates_p[ebp][ej + 3 * H];
            float ix = sigf(iv.x), iy = sigf(iv.y);
            float fx = sigf(fv.x), fy = sigf(fv.y);
            float gx = tanhfast(gv.x), gy = tanhfast(gv.y);
            float ox = sigf(ov.x), oy = sigf(ov.y);
            cst.x = fmaf(fx, cst.x, ix * gx);
            cst.y = fmaf(fy, cst.y, iy * gy);
            float2 hv = make_float2(ox * tanhfast(cst.x), oy * tanhfast(cst.y));
            hp[ebp][ej] = hv;
            int pairG = blockIdx.x * BPAIR + ebp;
            g_h1[dir][pairG][step][ej] = hv;
        }
        __syncthreads();
    }
}

// ---------------------------------------------------------------------------
// Layer-2: projection [T,100] x [100,8] + two scalar scans + output combine.
// grid = 512 blocks (one per batch pair), block = 128 threads.
// ---------------------------------------------------------------------------
__global__ __launch_bounds__(L2_THREADS) void lstm2_kernel(
    const float* __restrict__ Wih2f, const float* __restrict__ Whh2f,
    const float* __restrict__ bih2f, const float* __restrict__ bhh2f,
    const float* __restrict__ Wih2b, const float* __restrict__ Whh2b,
    const float* __restrict__ bih2b, const float* __restrict__ bhh2b,
    float* __restrict__ out)
{
    // S[0][t][k] : layer-2 fwd gate-input k at time t (x-part, no bias/recurrent)
    // S[1][s][k] : layer-2 bwd gate-input k at reversed step s
    __shared__ float2 S[2][T][4];                  // 32768 B
    __shared__ union {
        float2 tile[TCH][H];                       // 12800 B (phase A staging)
        float  hbuf[2][2][T];                      // 8192 B (phase B results)
    } u;
    __shared__ float Wp[2][8][H];                  // 3200 B

    const int pair = blockIdx.x;
    const int tid  = threadIdx.x;

    // Wp[r][k][j]: projection weights. r=0 acts on fwd h (cols 0..49 of W_ih2*),
    // r=1 acts on bwd-run h (cols 50..99). k<4 -> W_ih2f row k, k>=4 -> W_ih2b row k-4.
    for (int i = tid; i < 2 * 8 * H; i += L2_THREADS) {
        int r = i / (8 * H);
        int k = (i / H) % 8;
        int j = i % H;
        const float* W = (k < 4) ? Wih2f : Wih2b;
        Wp[r][k][j] = W[(k & 3) * 100 + r * H + j];
    }

    // ---- Phase A: projections, accumulated straight into S with run-reversal ----
    for (int r = 0; r < 2; r++) {
        const float2* __restrict__ src = &g_h1[r][pair][0][0];
        for (int c = 0; c < T / TCH; c++) {
            __syncthreads();
            for (int i = tid; i < TCH * H; i += L2_THREADS)
                ((float2*)u.tile)[i] = src[c * TCH * H + i];
            __syncthreads();
            #pragma unroll
            for (int it = 0; it < 2; it++) {
                int tl = tid / 8 + it * 16;
                int k  = tid % 8;
                float2 acc = make_float2(0.f, 0.f);
                #pragma unroll 10
                for (int j = 0; j < H; j++) {
                    float  w  = Wp[r][k][j];
                    float2 hv = u.tile[tl][j];
                    acc.x = fmaf(w, hv.x, acc.x);
                    acc.y = fmaf(w, hv.y, acc.y);
                }
                int ts = c * TCH + tl;
                int kk = k & 3;
                if (r == 0) {
                    if (k < 4) S[0][ts][kk] = acc;          // fwd-h -> fwd gates @ t
                    else       S[1][T - 1 - ts][kk] = acc;  // fwd-h -> bwd gates @ s=T-1-t
                } else {
                    if (k < 4) {
                        float2 p = S[0][T - 1 - ts][kk];    // bwd-run @ s -> fwd gates @ t=T-1-s
                        S[0][T - 1 - ts][kk] = make_float2(p.x + acc.x, p.y + acc.y);
                    } else {
                        float2 p = S[1][ts][kk];            // bwd-run @ s -> bwd gates @ s
                        S[1][ts][kk] = make_float2(p.x + acc.x, p.y + acc.y);
                    }
                }
            }
        }
    }
    __syncthreads();

    // ---- Phase B: 4 scalar scans (dir x batch-component) ----
    if (tid < 4) {
        int d    = tid >> 1;  // 0 fwd, 1 bwd
        int comp = tid & 1;   // 0 = even batch (.x), 1 = odd (.y)
        const float* whh = d ? Whh2b : Whh2f;
        const float* bi  = d ? bih2b : bih2f;
        const float* bh  = d ? bhh2b : bhh2f;
        float w0 = whh[0], w1 = whh[1], w2 = whh[2], w3 = whh[3];
        float bb0 = bi[0] + bh[0], bb1 = bi[1] + bh[1];
        float bb2 = bi[2] + bh[2], bb3 = bi[3] + bh[3];
        float h = 0.f, c = 0.f;
        for (int s = 0; s < T; s++) {
            float2 q0 = S[d][s][0], q1 = S[d][s][1], q2 = S[d][s][2], q3 = S[d][s][3];
            float gi = (comp ? q0.y : q0.x) + bb0 + h * w0;
            float gf = (comp ? q1.y : q1.x) + bb1 + h * w1;
            float gg = (comp ? q2.y : q2.x) + bb2 + h * w2;
            float go = (comp ? q3.y : q3.x) + bb3 + h * w3;
            float iv = sigf(gi), fv = sigf(gf), gv = tanhfast(gg), ov = sigf(go);
            c = fmaf(fv, c, iv * gv);
            h = ov * tanhfast(c);
            u.hbuf[d][comp][s] = h;
        }
    }
    __syncthreads();

    // out[b][0][t] = h_fwd[t] + h_bwd_run[T-1-t];  b = 2*pair + comp
    for (int i = tid; i < 2 * T; i += L2_THREADS) {
        int comp = i / T, t = i % T;
        out[(2 * pair + comp) * T + t] = u.hbuf[0][comp][t] + u.hbuf[1][comp][T - 1 - t];
    }
}

// ---------------------------------------------------------------------------
extern "C" void kernel_launch(void* const* d_in, const int* in_sizes, int n_in,
                              void* d_out, int out_size)
{
    const float* x     = (const float*)d_in[0];
    const float* Wih1f = (const float*)d_in[1];
    const float* Whh1f = (const float*)d_in[2];
    const float* bih1f = (const float*)d_in[3];
    const float* bhh1f = (const float*)d_in[4];
    const float* Wih1b = (const float*)d_in[5];
    const float* Whh1b = (const float*)d_in[6];
    const float* bih1b = (const float*)d_in[7];
    const float* bhh1b = (const float*)d_in[8];
    const float* Wih2f = (const float*)d_in[9];
    const float* Whh2f = (const float*)d_in[10];
    const float* bih2f = (const float*)d_in[11];
    const float* bhh2f = (const float*)d_in[12];
    const float* Wih2b = (const float*)d_in[13];
    const float* Whh2b = (const float*)d_in[14];
    const float* bih2b = (const float*)d_in[15];
    const float* bhh2b = (const float*)d_in[16];
    float* out = (float*)d_out;

    dim3 grid1(B / NB, 2);
    lstm1_kernel<<<grid1, L1_THREADS>>>(x, Wih1f, Whh1f, bih1f, bhh1f,
                                        Wih1b, Whh1b, bih1b, bhh1b);
    lstm2_kernel<<<NPAIR, L2_THREADS>>>(Wih2f, Whh2f, bih2f, bhh2f,
                                        Wih2b, Whh2b, bih2b, bhh2b, out);
}